// round 11
// baseline (speedup 1.0000x reference)
#include <cuda_runtime.h>

#define N_NODES 100000
#define N_EDGES 1600000
#define IN_DIM  128
#define HID_DIM 64
#define OUT_DIM 32
#define MAXD    64        // P(Poisson(16) > 64) ~ 1e-18: safe padded degree

// ---- device scratch (static globals: no runtime allocation allowed) ----
__device__ int   g_fill[N_NODES];             // becomes degree after scatter
__device__ int   g_slot[N_NODES * MAXD];      // padded adjacency (by dst)
__device__ float g_dinv[N_NODES];
__device__ float g_h1[N_NODES * HID_DIM];     // x @ W1
__device__ float g_a1[N_NODES * HID_DIM];     // relu(agg(h1) + b1)
__device__ float g_h2[N_NODES * OUT_DIM];     // a1 @ W2

__device__ __forceinline__ float* buf_sel(int sel) {
    switch (sel) {
        case 0: return g_h1;
        case 1: return g_a1;
        default: return g_h2;
    }
}

// ---- f32x2 packed helpers (FFMA2: 2x fp32 FMA throughput, exact IEEE) ----
__device__ __forceinline__ unsigned long long ffma2(
    unsigned long long a, unsigned long long b, unsigned long long c) {
    unsigned long long d;
    asm("fma.rn.f32x2 %0, %1, %2, %3;" : "=l"(d) : "l"(a), "l"(b), "l"(c));
    return d;
}
__device__ __forceinline__ unsigned long long pack2(float x) {
    unsigned long long d;
    asm("mov.b64 %0, {%1, %1};" : "=l"(d) : "f"(x));
    return d;
}

// ---------------------------------------------------------------- CSR build
__global__ void zero_fill_kernel() {
    int i = blockIdx.x * blockDim.x + threadIdx.x;
    if (i * 4 < N_NODES) {
        int4 z = {0, 0, 0, 0};
        if (i * 4 + 3 < N_NODES) *(int4*)&g_fill[i * 4] = z;
        else for (int k = i * 4; k < N_NODES; k++) g_fill[k] = 0;
    }
}

// 2 edges per thread; position-assign + store into padded slots.
__global__ void scatter_kernel(const int* __restrict__ ei) {
    int t = blockIdx.x * blockDim.x + threadIdx.x;
    int e = t * 2;
    if (e + 2 <= N_EDGES) {
        int2 s2 = *(const int2*)&ei[e];
        int2 d2 = *(const int2*)&ei[N_EDGES + e];
        if ((unsigned)s2.x < N_NODES && (unsigned)d2.x < N_NODES) {
            int p = atomicAdd(&g_fill[d2.x], 1);
            if (p < MAXD) g_slot[d2.x * MAXD + p] = s2.x;
        }
        if ((unsigned)s2.y < N_NODES && (unsigned)d2.y < N_NODES) {
            int p = atomicAdd(&g_fill[d2.y], 1);
            if (p < MAXD) g_slot[d2.y * MAXD + p] = s2.y;
        }
    } else if (e < N_EDGES) {
        unsigned src = (unsigned)ei[e];
        unsigned dst = (unsigned)ei[N_EDGES + e];
        if (src < N_NODES && dst < N_NODES) {
            int p = atomicAdd(&g_fill[dst], 1);
            if (p < MAXD) g_slot[dst * MAXD + p] = (int)src;
        }
    }
}

__global__ void dinv_kernel() {
    int i = blockIdx.x * blockDim.x + threadIdx.x;
    if (i < N_NODES) g_dinv[i] = rsqrtf((float)(g_fill[i] + 1));  // +1 self loop
}

// ---------------------------------------------------------------- GEMM (f32x2)
// TR=2 rows x CPT=16 cols per thread; ~70 regs -> 3 CTAs/SM (24 warps) so
// LDS latency is hidden and the kernel is FFMA2-pipe bound.
template <int FIN, int FOUT, int TR, int CPT, int XSEL>
__launch_bounds__(256, 3)
__global__ void gemm_kernel(const float* __restrict__ Xarg,
                            const float* __restrict__ W,
                            int out_sel) {
    constexpr int CG = FOUT / CPT;
    constexpr int RG = 256 / CG;
    constexpr int RB = RG * TR;
    constexpr int C2 = CPT / 2;    // packed f32x2 accumulators per row

    const float* X = (XSEL < 0) ? Xarg : buf_sel(XSEL);
    float* H = buf_sel(out_sel);

    __shared__ float Ws[FIN * FOUT];
    for (int i = threadIdx.x; i < FIN * FOUT; i += 256) Ws[i] = W[i];
    __syncthreads();

    const int cg   = threadIdx.x % CG;
    const int rg   = threadIdx.x / CG;
    const int row0 = blockIdx.x * RB + rg * TR;

    unsigned long long acc[TR][C2];
#pragma unroll
    for (int r = 0; r < TR; r++)
#pragma unroll
        for (int c = 0; c < C2; c++) acc[r][c] = 0ull;

    const float4* X4 = (const float4*)X;
    int rowc[TR];
#pragma unroll
    for (int r = 0; r < TR; r++) {
        int row = row0 + r;
        rowc[r] = (row < N_NODES) ? row : (N_NODES - 1);
    }

#pragma unroll
    for (int kk = 0; kk < FIN / 4; kk++) {
        float4 xv[TR];
#pragma unroll
        for (int r = 0; r < TR; r++)
            xv[r] = X4[rowc[r] * (FIN / 4) + kk];
#pragma unroll
        for (int k4 = 0; k4 < 4; k4++) {
            unsigned long long wv[C2];
            const unsigned long long* Wp =
                (const unsigned long long*)&Ws[(kk * 4 + k4) * FOUT + cg * CPT];
#pragma unroll
            for (int c = 0; c < C2; c++) wv[c] = Wp[c];
#pragma unroll
            for (int r = 0; r < TR; r++) {
                float xk = (k4 == 0) ? xv[r].x : (k4 == 1) ? xv[r].y
                         : (k4 == 2) ? xv[r].z : xv[r].w;
                unsigned long long xx = pack2(xk);
#pragma unroll
                for (int c = 0; c < C2; c++)
                    acc[r][c] = ffma2(xx, wv[c], acc[r][c]);
            }
        }
    }

#pragma unroll
    for (int r = 0; r < TR; r++) {
        int row = row0 + r;
        if (row < N_NODES) {
            unsigned long long* Hp =
                (unsigned long long*)&H[row * FOUT + cg * CPT];
#pragma unroll
            for (int c = 0; c < C2; c++) Hp[c] = acc[r][c];
        }
    }
}

// ---------------------------------------------------------------- aggregate
// warp per node; float2 lanes (F=64) / scalar (F=32); 4-edge unroll for MLP.
template <bool RELU, int HSEL>
__global__ void agg64_kernel(const float* __restrict__ bias,
                             float* __restrict__ Oarg, int out_sel) {
    const float2* H2 = (const float2*)buf_sel(HSEL);
    float2* O2 = (float2*)((out_sel < 0) ? Oarg : buf_sel(out_sel));

    int node = (blockIdx.x * blockDim.x + threadIdx.x) >> 5;
    int lane = threadIdx.x & 31;
    if (node >= N_NODES) return;

    float di = g_dinv[node];
    float2 h = H2[node * 32 + lane];
    float ax = di * di * h.x, ay = di * di * h.y;

    int deg = g_fill[node];
    if (deg > MAXD) deg = MAXD;
    const int* sl = &g_slot[node * MAXD];
    int j = 0;
    for (; j + 4 <= deg; j += 4) {
        int s0 = sl[j], s1 = sl[j + 1], s2 = sl[j + 2], s3 = sl[j + 3];
        float w0 = di * g_dinv[s0], w1 = di * g_dinv[s1];
        float w2 = di * g_dinv[s2], w3 = di * g_dinv[s3];
        float2 v0 = H2[s0 * 32 + lane];
        float2 v1 = H2[s1 * 32 + lane];
        float2 v2 = H2[s2 * 32 + lane];
        float2 v3 = H2[s3 * 32 + lane];
        ax += w0 * v0.x + w1 * v1.x + w2 * v2.x + w3 * v3.x;
        ay += w0 * v0.y + w1 * v1.y + w2 * v2.y + w3 * v3.y;
    }
    for (; j < deg; j++) {
        int s = sl[j];
        float w = di * g_dinv[s];
        float2 v = H2[s * 32 + lane];
        ax += w * v.x; ay += w * v.y;
    }

    float2 bb = ((const float2*)bias)[lane];
    ax += bb.x; ay += bb.y;
    if (RELU) { ax = fmaxf(ax, 0.f); ay = fmaxf(ay, 0.f); }
    float2 o = {ax, ay};
    O2[node * 32 + lane] = o;
}

template <bool RELU, int HSEL>
__global__ void agg32_kernel(const float* __restrict__ bias,
                             float* __restrict__ Oarg, int out_sel) {
    const float* H = buf_sel(HSEL);
    float* O = (out_sel < 0) ? Oarg : buf_sel(out_sel);

    int node = (blockIdx.x * blockDim.x + threadIdx.x) >> 5;
    int lane = threadIdx.x & 31;
    if (node >= N_NODES) return;

    float di = g_dinv[node];
    float acc = di * di * H[node * 32 + lane];

    int deg = g_fill[node];
    if (deg > MAXD) deg = MAXD;
    const int* sl = &g_slot[node * MAXD];
    int j = 0;
    for (; j + 4 <= deg; j += 4) {
        int s0 = sl[j], s1 = sl[j + 1], s2 = sl[j + 2], s3 = sl[j + 3];
        float w0 = di * g_dinv[s0], w1 = di * g_dinv[s1];
        float w2 = di * g_dinv[s2], w3 = di * g_dinv[s3];
        acc += w0 * H[s0 * 32 + lane] + w1 * H[s1 * 32 + lane]
             + w2 * H[s2 * 32 + lane] + w3 * H[s3 * 32 + lane];
    }
    for (; j < deg; j++) {
        int s = sl[j];
        acc += di * g_dinv[s] * H[s * 32 + lane];
    }

    float v = acc + bias[lane];
    if (RELU) v = fmaxf(v, 0.f);
    O[node * 32 + lane] = v;
}

// ---------------------------------------------------------------- launch
extern "C" void kernel_launch(void* const* d_in, const int* in_sizes, int n_in,
                              void* d_out, int out_size) {
    const float* x  = (const float*)d_in[0];
    const int*   ei = (const int*)d_in[1];
    const float* W1 = (const float*)d_in[2];
    const float* b1 = (const float*)d_in[3];
    const float* W2 = (const float*)d_in[4];
    const float* b2 = (const float*)d_in[5];
    float*       out = (float*)d_out;

    // side stream + events for CSR || GEMM1 overlap (created once, reused)
    static cudaStream_t s_side = nullptr;
    static cudaEvent_t  s_fork = nullptr, s_join = nullptr;
    if (!s_side) {
        if (cudaStreamCreateWithFlags(&s_side, cudaStreamNonBlocking) != cudaSuccess)
            s_side = nullptr;
        cudaEventCreateWithFlags(&s_fork, cudaEventDisableTiming);
        cudaEventCreateWithFlags(&s_join, cudaEventDisableTiming);
    }
    cudaStream_t sc = s_side ? s_side : 0;

    // fork: adjacency build on side stream (no count/scan: padded buckets)
    if (s_side) {
        cudaEventRecord(s_fork, 0);
        cudaStreamWaitEvent(sc, s_fork, 0);
    }
    zero_fill_kernel<<<(N_NODES / 4 + 255) / 256, 256, 0, sc>>>();
    scatter_kernel<<<(N_EDGES / 2 + 255) / 256, 256, 0, sc>>>(ei);
    dinv_kernel<<<(N_NODES + 255) / 256, 256, 0, sc>>>();
    if (s_side) cudaEventRecord(s_join, sc);

    // concurrently on main stream: GEMM1  x@W1 -> g_h1 (f32x2, TR=2/CPT=16)
    gemm_kernel<IN_DIM, HID_DIM, 2, 16, -1>
        <<<(N_NODES + 127) / 128, 256>>>(x, W1, 0);

    // join: agg needs adjacency + g_h1
    if (s_side) cudaStreamWaitEvent(0, s_join, 0);

    agg64_kernel<true, 0><<<(N_NODES * 32 + 255) / 256, 256>>>(b1, nullptr, 1);

    gemm_kernel<HID_DIM, OUT_DIM, 2, 16, 1>
        <<<(N_NODES + 255) / 256, 256>>>(nullptr, W2, 2);
    agg32_kernel<false, 2><<<(N_NODES * 32 + 255) / 256, 256>>>(b2, out, -1);
}

// round 13
// speedup vs baseline: 1.1936x; 1.1936x over previous
#include <cuda_runtime.h>
#include <cstdint>

#define N_NODES 100000
#define N_EDGES 1600000
#define IN_DIM  128
#define HID_DIM 64
#define OUT_DIM 32
#define MAXD    64        // P(Poisson(16) > 64) ~ 1e-18: safe padded degree

// ---- device scratch (static globals: no runtime allocation allowed) ----
__device__ int   g_fill[N_NODES];             // becomes degree after scatter
__device__ int   g_slot[N_NODES * MAXD];      // padded adjacency (by dst)
__device__ float g_dinv[N_NODES];
__device__ float g_h1[N_NODES * HID_DIM];     // x @ W1
__device__ float g_a1[N_NODES * HID_DIM];     // relu(agg(h1) + b1)
__device__ float g_h2[N_NODES * OUT_DIM];     // a1 @ W2

__device__ __forceinline__ float* buf_sel(int sel) {
    switch (sel) {
        case 0: return g_h1;
        case 1: return g_a1;
        default: return g_h2;
    }
}

// ---- f32x2 packed helpers (FFMA2: 2x fp32 FMA throughput, exact IEEE) ----
__device__ __forceinline__ unsigned long long ffma2(
    unsigned long long a, unsigned long long b, unsigned long long c) {
    unsigned long long d;
    asm("fma.rn.f32x2 %0, %1, %2, %3;" : "=l"(d) : "l"(a), "l"(b), "l"(c));
    return d;
}
__device__ __forceinline__ unsigned long long pack2(float x) {
    unsigned long long d;
    asm("mov.b64 %0, {%1, %1};" : "=l"(d) : "f"(x));
    return d;
}
// LDS.128 into two packed u64 (no repack movs)
__device__ __forceinline__ void lds128_u64x2(
    unsigned long long& a, unsigned long long& b, uint32_t saddr) {
    asm volatile("ld.shared.v2.u64 {%0, %1}, [%2];"
                 : "=l"(a), "=l"(b) : "r"(saddr));
}

// ---------------------------------------------------------------- CSR build
__global__ void zero_fill_kernel() {
    int i = blockIdx.x * blockDim.x + threadIdx.x;
    if (i * 4 < N_NODES) {
        int4 z = {0, 0, 0, 0};
        if (i * 4 + 3 < N_NODES) *(int4*)&g_fill[i * 4] = z;
        else for (int k = i * 4; k < N_NODES; k++) g_fill[k] = 0;
    }
}

// 2 edges per thread; position-assign + store into padded slots.
__global__ void scatter_kernel(const int* __restrict__ ei) {
    int t = blockIdx.x * blockDim.x + threadIdx.x;
    int e = t * 2;
    if (e + 2 <= N_EDGES) {
        int2 s2 = *(const int2*)&ei[e];
        int2 d2 = *(const int2*)&ei[N_EDGES + e];
        if ((unsigned)s2.x < N_NODES && (unsigned)d2.x < N_NODES) {
            int p = atomicAdd(&g_fill[d2.x], 1);
            if (p < MAXD) g_slot[d2.x * MAXD + p] = s2.x;
        }
        if ((unsigned)s2.y < N_NODES && (unsigned)d2.y < N_NODES) {
            int p = atomicAdd(&g_fill[d2.y], 1);
            if (p < MAXD) g_slot[d2.y * MAXD + p] = s2.y;
        }
    } else if (e < N_EDGES) {
        unsigned src = (unsigned)ei[e];
        unsigned dst = (unsigned)ei[N_EDGES + e];
        if (src < N_NODES && dst < N_NODES) {
            int p = atomicAdd(&g_fill[dst], 1);
            if (p < MAXD) g_slot[dst * MAXD + p] = (int)src;
        }
    }
}

__global__ void dinv_kernel() {
    int i = blockIdx.x * blockDim.x + threadIdx.x;
    if (i < N_NODES) g_dinv[i] = rsqrtf((float)(g_fill[i] + 1));  // +1 self loop
}

// ---------------------------------------------------------------- GEMM (f32x2)
// TR=4 rows x CPT=16 cols per thread; W fed via LDS.128 -> packed u64 pairs.
// 32 FFMA2 : 4 LDS per k-step; 2 CTAs/SM for latency hiding.
template <int FIN, int FOUT, int TR, int CPT, int XSEL>
__launch_bounds__(256, 2)
__global__ void gemm_kernel(const float* __restrict__ Xarg,
                            const float* __restrict__ W,
                            int out_sel) {
    constexpr int CG = FOUT / CPT;
    constexpr int RG = 256 / CG;
    constexpr int RB = RG * TR;
    constexpr int C2 = CPT / 2;    // packed f32x2 accumulators per row (8)
    constexpr int C4 = CPT / 4;    // LDS.128 loads per k-step (4)

    const float* X = (XSEL < 0) ? Xarg : buf_sel(XSEL);
    float* H = buf_sel(out_sel);

    __shared__ float Ws[FIN * FOUT];
    for (int i = threadIdx.x; i < FIN * FOUT; i += 256) Ws[i] = W[i];
    __syncthreads();

    const int cg   = threadIdx.x % CG;
    const int rg   = threadIdx.x / CG;
    const int row0 = blockIdx.x * RB + rg * TR;

    const uint32_t ws_col = (uint32_t)__cvta_generic_to_shared(Ws)
                          + (uint32_t)(cg * CPT * 4);

    unsigned long long acc[TR][C2];
#pragma unroll
    for (int r = 0; r < TR; r++)
#pragma unroll
        for (int c = 0; c < C2; c++) acc[r][c] = 0ull;

    const float4* X4 = (const float4*)X;
    int rowc[TR];
#pragma unroll
    for (int r = 0; r < TR; r++) {
        int row = row0 + r;
        rowc[r] = (row < N_NODES) ? row : (N_NODES - 1);
    }

#pragma unroll 4
    for (int kk = 0; kk < FIN / 4; kk++) {
        float4 xv[TR];
#pragma unroll
        for (int r = 0; r < TR; r++)
            xv[r] = X4[rowc[r] * (FIN / 4) + kk];
#pragma unroll
        for (int k4 = 0; k4 < 4; k4++) {
            unsigned long long wv[C2];
            uint32_t kaddr = ws_col + (uint32_t)((kk * 4 + k4) * FOUT * 4);
#pragma unroll
            for (int c = 0; c < C4; c++)
                lds128_u64x2(wv[c * 2], wv[c * 2 + 1], kaddr + c * 16);
#pragma unroll
            for (int r = 0; r < TR; r++) {
                float xk = (k4 == 0) ? xv[r].x : (k4 == 1) ? xv[r].y
                         : (k4 == 2) ? xv[r].z : xv[r].w;
                unsigned long long xx = pack2(xk);
#pragma unroll
                for (int c = 0; c < C2; c++)
                    acc[r][c] = ffma2(xx, wv[c], acc[r][c]);
            }
        }
    }

#pragma unroll
    for (int r = 0; r < TR; r++) {
        int row = row0 + r;
        if (row < N_NODES) {
            unsigned long long* Hp =
                (unsigned long long*)&H[row * FOUT + cg * CPT];
#pragma unroll
            for (int c = 0; c < C2; c++) Hp[c] = acc[r][c];
        }
    }
}

// ---------------------------------------------------------------- aggregate
// warp per node; float2 lanes (F=64) / scalar (F=32); 4-edge unroll for MLP.
template <bool RELU, int HSEL>
__global__ void agg64_kernel(const float* __restrict__ bias,
                             float* __restrict__ Oarg, int out_sel) {
    const float2* H2 = (const float2*)buf_sel(HSEL);
    float2* O2 = (float2*)((out_sel < 0) ? Oarg : buf_sel(out_sel));

    int node = (blockIdx.x * blockDim.x + threadIdx.x) >> 5;
    int lane = threadIdx.x & 31;
    if (node >= N_NODES) return;

    float di = g_dinv[node];
    float2 h = H2[node * 32 + lane];
    float ax = di * di * h.x, ay = di * di * h.y;

    int deg = g_fill[node];
    if (deg > MAXD) deg = MAXD;
    const int* sl = &g_slot[node * MAXD];
    int j = 0;
    for (; j + 4 <= deg; j += 4) {
        int s0 = sl[j], s1 = sl[j + 1], s2 = sl[j + 2], s3 = sl[j + 3];
        float w0 = di * g_dinv[s0], w1 = di * g_dinv[s1];
        float w2 = di * g_dinv[s2], w3 = di * g_dinv[s3];
        float2 v0 = H2[s0 * 32 + lane];
        float2 v1 = H2[s1 * 32 + lane];
        float2 v2 = H2[s2 * 32 + lane];
        float2 v3 = H2[s3 * 32 + lane];
        ax += w0 * v0.x + w1 * v1.x + w2 * v2.x + w3 * v3.x;
        ay += w0 * v0.y + w1 * v1.y + w2 * v2.y + w3 * v3.y;
    }
    for (; j < deg; j++) {
        int s = sl[j];
        float w = di * g_dinv[s];
        float2 v = H2[s * 32 + lane];
        ax += w * v.x; ay += w * v.y;
    }

    float2 bb = ((const float2*)bias)[lane];
    ax += bb.x; ay += bb.y;
    if (RELU) { ax = fmaxf(ax, 0.f); ay = fmaxf(ay, 0.f); }
    float2 o = {ax, ay};
    O2[node * 32 + lane] = o;
}

template <bool RELU, int HSEL>
__global__ void agg32_kernel(const float* __restrict__ bias,
                             float* __restrict__ Oarg, int out_sel) {
    const float* H = buf_sel(HSEL);
    float* O = (out_sel < 0) ? Oarg : buf_sel(out_sel);

    int node = (blockIdx.x * blockDim.x + threadIdx.x) >> 5;
    int lane = threadIdx.x & 31;
    if (node >= N_NODES) return;

    float di = g_dinv[node];
    float acc = di * di * H[node * 32 + lane];

    int deg = g_fill[node];
    if (deg > MAXD) deg = MAXD;
    const int* sl = &g_slot[node * MAXD];
    int j = 0;
    for (; j + 4 <= deg; j += 4) {
        int s0 = sl[j], s1 = sl[j + 1], s2 = sl[j + 2], s3 = sl[j + 3];
        float w0 = di * g_dinv[s0], w1 = di * g_dinv[s1];
        float w2 = di * g_dinv[s2], w3 = di * g_dinv[s3];
        acc += w0 * H[s0 * 32 + lane] + w1 * H[s1 * 32 + lane]
             + w2 * H[s2 * 32 + lane] + w3 * H[s3 * 32 + lane];
    }
    for (; j < deg; j++) {
        int s = sl[j];
        acc += di * g_dinv[s] * H[s * 32 + lane];
    }

    float v = acc + bias[lane];
    if (RELU) v = fmaxf(v, 0.f);
    O[node * 32 + lane] = v;
}

// ---------------------------------------------------------------- launch
extern "C" void kernel_launch(void* const* d_in, const int* in_sizes, int n_in,
                              void* d_out, int out_size) {
    const float* x  = (const float*)d_in[0];
    const int*   ei = (const int*)d_in[1];
    const float* W1 = (const float*)d_in[2];
    const float* b1 = (const float*)d_in[3];
    const float* W2 = (const float*)d_in[4];
    const float* b2 = (const float*)d_in[5];
    float*       out = (float*)d_out;

    // side stream + events for CSR || GEMM1 overlap (created once, reused)
    static cudaStream_t s_side = nullptr;
    static cudaEvent_t  s_fork = nullptr, s_join = nullptr;
    if (!s_side) {
        if (cudaStreamCreateWithFlags(&s_side, cudaStreamNonBlocking) != cudaSuccess)
            s_side = nullptr;
        cudaEventCreateWithFlags(&s_fork, cudaEventDisableTiming);
        cudaEventCreateWithFlags(&s_join, cudaEventDisableTiming);
    }
    cudaStream_t sc = s_side ? s_side : 0;

    // fork: adjacency build on side stream (no count/scan: padded buckets)
    if (s_side) {
        cudaEventRecord(s_fork, 0);
        cudaStreamWaitEvent(sc, s_fork, 0);
    }
    zero_fill_kernel<<<(N_NODES / 4 + 255) / 256, 256, 0, sc>>>();
    scatter_kernel<<<(N_EDGES / 2 + 255) / 256, 256, 0, sc>>>(ei);
    dinv_kernel<<<(N_NODES + 255) / 256, 256, 0, sc>>>();
    if (s_side) cudaEventRecord(s_join, sc);

    // concurrently on main stream: GEMM1  x@W1 -> g_h1 (f32x2, TR=4/CPT=16)
    gemm_kernel<IN_DIM, HID_DIM, 4, 16, -1>
        <<<(N_NODES + 255) / 256, 256>>>(x, W1, 0);

    // join: agg needs adjacency + g_h1
    if (s_side) cudaStreamWaitEvent(0, s_join, 0);

    agg64_kernel<true, 0><<<(N_NODES * 32 + 255) / 256, 256>>>(b1, nullptr, 1);

    gemm_kernel<HID_DIM, OUT_DIM, 4, 16, 1>
        <<<(N_NODES + 511) / 512, 256>>>(nullptr, W2, 2);
    agg32_kernel<false, 2><<<(N_NODES * 32 + 255) / 256, 256>>>(b2, out, -1);
}